// round 5
// baseline (speedup 1.0000x reference)
#include <cuda_runtime.h>
#include <math.h>

#define BB   256
#define HH   32
#define WW   32
#define AA   5
#define NCC  20
#define MM   50
#define NOBJ (BB*MM)

#define GRID    592                    // 4 blocks/SM * 148 SMs, single wave
#define NTHR    256
#define TOTTHR  (GRID*NTHR)            // 151552
#define NF4     (BB*AA*256)            // 327680 conf float4s

// Zero-init at load; last block resets accumulators each launch -> replay-safe.
__device__ float    g_acc[4];
__device__ unsigned g_cnt;

__device__ __forceinline__ float sigm(float x) { return 1.0f / (1.0f + __expf(-x)); }

__global__ void __launch_bounds__(256)
fused_loss_kernel(const float* __restrict__ out,
                  const float4* __restrict__ gt_boxes,
                  const float* __restrict__ anchor,
                  const int* __restrict__ gt_classes,
                  const int* __restrict__ num_box,
                  float* __restrict__ dout) {
    float boxl = 0.0f, confl = 0.0f, noobj = 0.0f, clsl = 0.0f;

    // ---- sparse: objects strided across blocks (block k, lane t -> t*GRID+k) ----
    // Runs in warp 0 only; its scattered long-latency loads overlap the other
    // warps' dense streaming.
    {
        int i = threadIdx.x * GRID + blockIdx.x;    // object id
        if (threadIdx.x < 22 && i < NOBJ) {
            int b = i / MM;
            int m = i - b * MM;
            int nb = num_box[b];
            if (nb > MM) nb = MM;
            if (m < nb) {
                float4 box = gt_boxes[i];
                float tx = box.x * (float)HH;
                float ty = box.y * (float)HH;
                int wq = (int)floorf(tx);
                int hq = (int)floorf(ty);
                int mycell = hq * WW + wq;

                // Winner = max m in my cell; class = min among colliders.
                int last = -1, minc = 1 << 30;
                const float4* row = gt_boxes + b * MM;
                for (int m2 = 0; m2 < nb; m2++) {
                    float4 b2 = row[m2];
                    int c2 = ((int)floorf(b2.y * (float)HH)) * WW
                           +  (int)floorf(b2.x * (float)HH);
                    if (c2 == mycell) {
                        last = m2;
                        int cc = gt_classes[b * MM + m2];
                        minc = (cc < minc) ? cc : minc;
                    }
                }

                if (last == m) {
                    int cls = minc;
                    const float* cellb = out + (size_t)b * 125 * 1024 + mycell;

                    float tw = box.z * (float)HH;
                    float th = box.w * (float)HH;
                    float tx1 = tx - tw * 0.5f, ty1 = ty - th * 0.5f;
                    float tx2 = tx + tw * 0.5f, ty2 = ty + th * 0.5f;
                    float tarea = tw * th;

                    float best_iou = -1.0f;
                    int   best = 0;
                    float bx = 0, by = 0, bw = 0, bh = 0, pcb = 0;
                    #pragma unroll
                    for (int a = 0; a < AA; a++) {
                        const float* ab = cellb + a * 25 * 1024;
                        float pconf = sigm(ab[NCC * 1024]);
                        float sx = sigm(ab[(NCC + 1) * 1024]);
                        float sy = sigm(ab[(NCC + 2) * 1024]);
                        float pw = __expf(ab[(NCC + 3) * 1024]) * anchor[a * 2 + 0];
                        float ph = __expf(ab[(NCC + 4) * 1024]) * anchor[a * 2 + 1];
                        float px = (float)wq + sx;
                        float py = (float)hq + sy;
                        float ax1 = px - pw * 0.5f, ay1 = py - ph * 0.5f;
                        float ax2 = px + pw * 0.5f, ay2 = py + ph * 0.5f;
                        float iw = fmaxf(fminf(ax2, tx2) - fmaxf(ax1, tx1), 0.0f);
                        float ih = fmaxf(fminf(ay2, ty2) - fmaxf(ay1, ty1), 0.0f);
                        float inter = iw * ih;
                        float uni = pw * ph + tarea - inter;
                        float iou = inter / fmaxf(uni, 1e-10f);
                        if (iou > best_iou) {   // strict >: first max wins
                            best_iou = iou; best = a;
                            bx = px; by = py; bw = pw; bh = ph; pcb = pconf;
                        }
                    }

                    float d0 = bx - tx;
                    float d1 = by - ty;
                    float d2 = sqrtf(bw) - sqrtf(tw);
                    float d3 = sqrtf(bh) - sqrtf(th);
                    boxl = d0 * d0 + d1 * d1 + d2 * d2 + d3 * d3;

                    confl = (pcb - 1.0f) * (pcb - 1.0f);
                    noobj = -pcb * pcb;        // remove best anchor from noobj

                    const float* cb = cellb + (size_t)best * 25 * 1024;
                    float mx = -1e30f, lc = 0.0f;
                    float l[NCC];
                    #pragma unroll
                    for (int c = 0; c < NCC; c++) {
                        l[c] = cb[c * 1024];
                        mx = fmaxf(mx, l[c]);
                        lc = (c == cls) ? l[c] : lc;
                    }
                    float sum = 0.0f;
                    #pragma unroll
                    for (int c = 0; c < NCC; c++) sum += __expf(l[c] - mx);
                    clsl = mx + __logf(sum) - lc;
                }
            }
        }
    }

    // ---- dense: grid-stride over all conf float4s ----
    {
        int gid = blockIdx.x * NTHR + threadIdx.x;
        for (int t = gid; t < NF4; t += TOTTHR) {
            int b = t / (AA * 256);
            int r = t - b * (AA * 256);
            int a = r >> 8;
            int q = r & 255;
            float4 v = ((const float4*)out)[(size_t)(b * 125 + a * 25 + NCC) * 256 + q];
            float s;
            s = sigm(v.x); noobj += s * s;
            s = sigm(v.y); noobj += s * s;
            s = sigm(v.z); noobj += s * s;
            s = sigm(v.w); noobj += s * s;
        }
    }

    // ---- block reduction ----
    #pragma unroll
    for (int off = 16; off > 0; off >>= 1) {
        boxl  += __shfl_down_sync(0xffffffffu, boxl,  off);
        confl += __shfl_down_sync(0xffffffffu, confl, off);
        noobj += __shfl_down_sync(0xffffffffu, noobj, off);
        clsl  += __shfl_down_sync(0xffffffffu, clsl,  off);
    }
    __shared__ float sm[4][8];
    int lane = threadIdx.x & 31;
    int wid  = threadIdx.x >> 5;
    if (lane == 0) {
        sm[0][wid] = boxl; sm[1][wid] = confl;
        sm[2][wid] = noobj; sm[3][wid] = clsl;
    }
    __syncthreads();
    if (threadIdx.x == 0) {
        float s0 = 0, s1 = 0, s2 = 0, s3 = 0;
        #pragma unroll
        for (int k = 0; k < 8; k++) {
            s0 += sm[0][k]; s1 += sm[1][k]; s2 += sm[2][k]; s3 += sm[3][k];
        }
        if (s0 != 0.0f) atomicAdd(&g_acc[0], s0);
        if (s1 != 0.0f) atomicAdd(&g_acc[1], s1);
        atomicAdd(&g_acc[2], s2);
        if (s3 != 0.0f) atomicAdd(&g_acc[3], s3);
        __threadfence();
        unsigned old = atomicInc(&g_cnt, GRID - 1);
        if (old == GRID - 1) {                  // last block finalizes
            volatile float* a = g_acc;
            dout[0] = a[0] * (5.0f / 256.0f);   // LAM_COORD / B
            dout[1] = a[1] * (1.0f / 256.0f);   // LAM_OBJ   / B
            dout[2] = a[2] * (0.5f / 256.0f);   // LAM_NOOBJ / B
            dout[3] = a[3] * (1.0f / 256.0f);   // LAM_CLS   / B
            g_acc[0] = 0.0f; g_acc[1] = 0.0f;   // reset for next replay
            g_acc[2] = 0.0f; g_acc[3] = 0.0f;
        }
    }
}

extern "C" void kernel_launch(void* const* d_in, const int* in_sizes, int n_in,
                              void* d_out, int out_size) {
    const float*  out_t      = (const float*)d_in[0];
    const float4* gt_boxes   = (const float4*)d_in[1];
    const float*  anchor     = (const float*)d_in[2];
    const int*    gt_classes = (const int*)d_in[3];
    const int*    num_box    = (const int*)d_in[4];
    float* dout = (float*)d_out;

    fused_loss_kernel<<<GRID, NTHR>>>(out_t, gt_boxes, anchor,
                                      gt_classes, num_box, dout);
}

// round 7
// speedup vs baseline: 1.2557x; 1.2557x over previous
#include <cuda_runtime.h>
#include <math.h>

#define BB   256
#define HH   32
#define WW   32
#define AA   5
#define NCC  20
#define MM   50
#define NOBJ (BB*MM)

#define GRID    592                    // 4 blocks/SM * 148 SMs, single wave
#define NTHR    256
#define TOTTHR  (GRID*NTHR)            // 151552
#define NF4     (BB*AA*256)            // 327680 conf float4s
#define OBJ_PER_BLK 22                 // 592*22 = 13024 >= 12800

// Zero-init at load; last block resets accumulators each launch -> replay-safe.
__device__ float    g_acc[4];
__device__ unsigned g_cnt;

__device__ __forceinline__ float sigm(float x) { return 1.0f / (1.0f + __expf(-x)); }

__global__ void __launch_bounds__(256)
fused_loss_kernel(const float* __restrict__ out,
                  const float4* __restrict__ gt_boxes,
                  const float* __restrict__ anchor,
                  const int* __restrict__ gt_classes,
                  const int* __restrict__ num_box,
                  float* __restrict__ dout) {
    float boxl = 0.0f, confl = 0.0f, noobj = 0.0f, clsl = 0.0f;

    // ---- sparse: contiguous 22-object chunk per block (warp 0, lanes 0-21).
    // Contiguous chunk spans <=2 batches -> gt-scan row loads broadcast in-warp.
    {
        int i = blockIdx.x * OBJ_PER_BLK + threadIdx.x;    // object id
        if (threadIdx.x < OBJ_PER_BLK && i < NOBJ) {
            int b = i / MM;
            int m = i - b * MM;
            int nb = num_box[b];
            if (nb > MM) nb = MM;
            if (m < nb) {
                float4 box = gt_boxes[i];
                float tx = box.x * (float)HH;
                float ty = box.y * (float)HH;
                int wq = (int)floorf(tx);
                int hq = (int)floorf(ty);
                int mycell = hq * WW + wq;

                // Winner = max m in my cell; class = min among colliders.
                int last = -1, minc = 1 << 30;
                const float4* row = gt_boxes + b * MM;
                const int*    crow = gt_classes + b * MM;
                for (int m2 = 0; m2 < nb; m2++) {
                    float4 b2 = row[m2];
                    int c2 = ((int)floorf(b2.y * (float)HH)) * WW
                           +  (int)floorf(b2.x * (float)HH);
                    if (c2 == mycell) {
                        last = m2;
                        int cc = crow[m2];
                        minc = (cc < minc) ? cc : minc;
                    }
                }

                if (last == m) {             // this thread owns the cell
                    int cls = minc;
                    const float* cellb = out + (size_t)b * 125 * 1024 + mycell;

                    float tw = box.z * (float)HH;
                    float th = box.w * (float)HH;
                    float tx1 = tx - tw * 0.5f, ty1 = ty - th * 0.5f;
                    float tx2 = tx + tw * 0.5f, ty2 = ty + th * 0.5f;
                    float tarea = tw * th;

                    float best_iou = -1.0f;
                    int   best = 0;
                    float bx = 0, by = 0, bw = 0, bh = 0, pcb = 0;
                    #pragma unroll
                    for (int a = 0; a < AA; a++) {
                        const float* ab = cellb + a * 25 * 1024;
                        float pconf = sigm(ab[NCC * 1024]);
                        float sx = sigm(ab[(NCC + 1) * 1024]);
                        float sy = sigm(ab[(NCC + 2) * 1024]);
                        float pw = __expf(ab[(NCC + 3) * 1024]) * anchor[a * 2 + 0];
                        float ph = __expf(ab[(NCC + 4) * 1024]) * anchor[a * 2 + 1];
                        float px = (float)wq + sx;
                        float py = (float)hq + sy;
                        float ax1 = px - pw * 0.5f, ay1 = py - ph * 0.5f;
                        float ax2 = px + pw * 0.5f, ay2 = py + ph * 0.5f;
                        float iw = fmaxf(fminf(ax2, tx2) - fmaxf(ax1, tx1), 0.0f);
                        float ih = fmaxf(fminf(ay2, ty2) - fmaxf(ay1, ty1), 0.0f);
                        float inter = iw * ih;
                        float uni = pw * ph + tarea - inter;
                        float iou = inter / fmaxf(uni, 1e-10f);
                        if (iou > best_iou) {   // strict >: first max wins
                            best_iou = iou; best = a;
                            bx = px; by = py; bw = pw; bh = ph; pcb = pconf;
                        }
                    }

                    float d0 = bx - tx;
                    float d1 = by - ty;
                    float d2 = sqrtf(bw) - sqrtf(tw);
                    float d3 = sqrtf(bh) - sqrtf(th);
                    boxl = d0 * d0 + d1 * d1 + d2 * d2 + d3 * d3;

                    confl = (pcb - 1.0f) * (pcb - 1.0f);
                    noobj = -pcb * pcb;        // remove best anchor from noobj

                    const float* cb = cellb + (size_t)best * 25 * 1024;
                    float mx = -1e30f, lc = 0.0f;
                    float l[NCC];
                    #pragma unroll
                    for (int c = 0; c < NCC; c++) {
                        l[c] = cb[c * 1024];
                        mx = fmaxf(mx, l[c]);
                        lc = (c == cls) ? l[c] : lc;
                    }
                    float sum = 0.0f;
                    #pragma unroll
                    for (int c = 0; c < NCC; c++) sum += __expf(l[c] - mx);
                    clsl = mx + __logf(sum) - lc;
                }
            }
        }
    }

    // ---- dense: grid-stride over all conf float4s ----
    {
        int gid = blockIdx.x * NTHR + threadIdx.x;
        for (int t = gid; t < NF4; t += TOTTHR) {
            int b = t / (AA * 256);
            int r = t - b * (AA * 256);
            int a = r >> 8;
            int q = r & 255;
            float4 v = ((const float4*)out)[(size_t)(b * 125 + a * 25 + NCC) * 256 + q];
            float s;
            s = sigm(v.x); noobj += s * s;
            s = sigm(v.y); noobj += s * s;
            s = sigm(v.z); noobj += s * s;
            s = sigm(v.w); noobj += s * s;
        }
    }

    // ---- block reduction ----
    #pragma unroll
    for (int off = 16; off > 0; off >>= 1) {
        boxl  += __shfl_down_sync(0xffffffffu, boxl,  off);
        confl += __shfl_down_sync(0xffffffffu, confl, off);
        noobj += __shfl_down_sync(0xffffffffu, noobj, off);
        clsl  += __shfl_down_sync(0xffffffffu, clsl,  off);
    }
    __shared__ float sm[4][8];
    int lane = threadIdx.x & 31;
    int wid  = threadIdx.x >> 5;
    if (lane == 0) {
        sm[0][wid] = boxl; sm[1][wid] = confl;
        sm[2][wid] = noobj; sm[3][wid] = clsl;
    }
    __syncthreads();
    if (threadIdx.x == 0) {
        float s0 = 0, s1 = 0, s2 = 0, s3 = 0;
        #pragma unroll
        for (int k = 0; k < 8; k++) {
            s0 += sm[0][k]; s1 += sm[1][k]; s2 += sm[2][k]; s3 += sm[3][k];
        }
        if (s0 != 0.0f) atomicAdd(&g_acc[0], s0);
        if (s1 != 0.0f) atomicAdd(&g_acc[1], s1);
        atomicAdd(&g_acc[2], s2);
        if (s3 != 0.0f) atomicAdd(&g_acc[3], s3);
        __threadfence();
        unsigned old = atomicInc(&g_cnt, GRID - 1);
        if (old == GRID - 1) {                  // last block finalizes
            volatile float* a = g_acc;
            dout[0] = a[0] * (5.0f / 256.0f);   // LAM_COORD / B
            dout[1] = a[1] * (1.0f / 256.0f);   // LAM_OBJ   / B
            dout[2] = a[2] * (0.5f / 256.0f);   // LAM_NOOBJ / B
            dout[3] = a[3] * (1.0f / 256.0f);   // LAM_CLS   / B
            g_acc[0] = 0.0f; g_acc[1] = 0.0f;   // reset for next replay
            g_acc[2] = 0.0f; g_acc[3] = 0.0f;
        }
    }
}

extern "C" void kernel_launch(void* const* d_in, const int* in_sizes, int n_in,
                              void* d_out, int out_size) {
    const float*  out_t      = (const float*)d_in[0];
    const float4* gt_boxes   = (const float4*)d_in[1];
    const float*  anchor     = (const float*)d_in[2];
    const int*    gt_classes = (const int*)d_in[3];
    const int*    num_box    = (const int*)d_in[4];
    float* dout = (float*)d_out;

    fused_loss_kernel<<<GRID, NTHR>>>(out_t, gt_boxes, anchor,
                                      gt_classes, num_box, dout);
}

// round 8
// speedup vs baseline: 1.4047x; 1.1186x over previous
#include <cuda_runtime.h>
#include <math.h>

#define BB   256
#define HH   32
#define WW   32
#define AA   5
#define NCC  20
#define MM   50
#define NOBJ (BB*MM)

#define GRID    592                    // 4 blocks/SM * 148 SMs, single wave
#define NTHR    256
#define TOTTHR  (GRID*NTHR)            // 151552
#define NF4     (BB*AA*256)            // 327680 conf float4s
#define OPB     22                     // objects per block: 592*22 >= 12800

// Zero-init at load; last block resets accumulators each launch -> replay-safe.
__device__ float    g_acc[4];
__device__ unsigned g_cnt;

__device__ __forceinline__ float sigm(float x) { return 1.0f / (1.0f + __expf(-x)); }

__global__ void __launch_bounds__(256)
fused_loss_kernel(const float* __restrict__ out,
                  const float4* __restrict__ gt_boxes,
                  const float* __restrict__ anchor,
                  const int* __restrict__ gt_classes,
                  const int* __restrict__ num_box,
                  float* __restrict__ dout) {
    __shared__ int    s_cell[2 * MM];   // cells of this block's (<=2) batches
    __shared__ int    s_cls [2 * MM];
    __shared__ int    s_meta[OPB];      // packed b | cell<<8 | cls<<18
    __shared__ float4 s_box [OPB];      // tx,ty,tw,th (already *32)
    __shared__ int    s_nrec;
    __shared__ float  sm[4][8];

    int tid  = threadIdx.x;
    int lane = tid & 31;
    int wid  = tid >> 5;
    float boxl = 0.0f, confl = 0.0f, noobj = 0.0f, clsl = 0.0f;

    int i0 = blockIdx.x * OPB;
    int b0 = i0 / MM;

    // ---- phase 0: precompute cells/classes of the two candidate batches ----
    if (tid == 0) s_nrec = 0;
    if (tid < 2 * MM) {
        int bb = b0 + tid / MM;
        int m2 = tid % MM;
        int cellv = -1, clsv = 0;
        if (bb < BB) {
            int nb = num_box[bb]; if (nb > MM) nb = MM;
            if (m2 < nb) {
                float4 bx = gt_boxes[bb * MM + m2];
                int gx = (int)floorf(bx.x * 32.0f);
                int gy = (int)floorf(bx.y * 32.0f);
                cellv = gy * WW + gx;
                clsv  = gt_classes[bb * MM + m2];
            }
        }
        s_cell[tid] = cellv;
        s_cls [tid] = clsv;
    }
    __syncthreads();

    // ---- phase 1: winner scan over smem + compaction (lanes 0-21, warp 0) ----
    if (tid < OPB) {
        int i = i0 + tid;
        if (i < NOBJ) {
            int bb = i / MM;
            int m  = i - bb * MM;
            int base = (bb - b0) * MM;
            int mycell = s_cell[base + m];
            if (mycell >= 0) {
                int last = -1, minc = 1 << 30;
                #pragma unroll
                for (int m2 = 0; m2 < MM; m2++) {
                    int c2 = s_cell[base + m2];     // invalid entries are -1
                    if (c2 == mycell) {
                        last = m2;
                        int cc = s_cls[base + m2];
                        minc = (cc < minc) ? cc : minc;
                    }
                }
                if (last == m) {                    // this object owns the cell
                    int r = atomicAdd(&s_nrec, 1);
                    s_meta[r] = bb | (mycell << 8) | (minc << 18);
                    float4 bx = gt_boxes[i];
                    s_box[r] = make_float4(bx.x * 32.0f, bx.y * 32.0f,
                                           bx.z * 32.0f, bx.w * 32.0f);
                }
            }
        }
    }
    __syncthreads();

    // ---- phase 2: warp-cooperative winner processing ----
    {
        const unsigned FULL = 0xffffffffu;
        int a_id = lane / 5, ch = lane - a_id * 5;        // for lane<25
        float anc = 1.0f;
        if (lane < 25 && ch >= 3) anc = anchor[2 * a_id + (ch - 3)];
        int nrec = s_nrec;
        for (int r = wid; r < nrec; r += 8) {
            int   meta = s_meta[r];
            float4 tb  = s_box[r];
            int bb   = meta & 255;
            int cell = (meta >> 8) & 1023;
            int cls  = (meta >> 18) & 31;
            const float* cellb = out + (size_t)bb * 128000 + cell;
            int wq = cell & 31, hq = (cell >> 5) & 31;

            // one LDG: 25 anchor-stat values in flight at once
            float v = 0.0f;
            if (lane < 25) v = cellb[(a_id * 25 + NCC + ch) * 1024];
            float tval = (ch <= 2) ? sigm(v) : __expf(v) * anc;
            float s1 = __shfl_sync(FULL, tval, lane + 1);
            float s2 = __shfl_sync(FULL, tval, lane + 2);
            float s3 = __shfl_sync(FULL, tval, lane + 3);
            float s4 = __shfl_sync(FULL, tval, lane + 4);

            float tx = tb.x, ty = tb.y, tw = tb.z, th = tb.w;
            float tx1 = tx - tw * 0.5f, ty1 = ty - th * 0.5f;
            float tx2 = tx + tw * 0.5f, ty2 = ty + th * 0.5f;
            float tarea = tw * th;

            float iou = -2.0f, px = 0, py = 0, pw = 0, ph = 0, pconf = 0;
            if (lane < 25 && ch == 0) {               // anchor-lead lanes
                pconf = tval;
                px = (float)wq + s1; py = (float)hq + s2;
                pw = s3; ph = s4;
                float ax1 = px - pw * 0.5f, ay1 = py - ph * 0.5f;
                float ax2 = px + pw * 0.5f, ay2 = py + ph * 0.5f;
                float iw = fmaxf(fminf(ax2, tx2) - fmaxf(ax1, tx1), 0.0f);
                float ih = fmaxf(fminf(ay2, ty2) - fmaxf(ay1, ty1), 0.0f);
                float inter = iw * ih;
                float uni = pw * ph + tarea - inter;
                iou = inter / fmaxf(uni, 1e-10f);
            }
            // argmax over 5 anchors, identical on all lanes (first max wins)
            float bi = -1.0f; int best = 0;
            float bx = 0, by = 0, bw = 0, bh = 0, pcb = 0;
            #pragma unroll
            for (int a = 0; a < AA; a++) {
                float ia = __shfl_sync(FULL, iou,   a * 5);
                float xa = __shfl_sync(FULL, px,    a * 5);
                float ya = __shfl_sync(FULL, py,    a * 5);
                float wa = __shfl_sync(FULL, pw,    a * 5);
                float ha = __shfl_sync(FULL, ph,    a * 5);
                float ca = __shfl_sync(FULL, pconf, a * 5);
                if (ia > bi) { bi = ia; best = a; bx = xa; by = ya; bw = wa; bh = ha; pcb = ca; }
            }

            // one LDG: the best anchor's 20 class logits; shfl softmax
            float lv = (lane < NCC) ? cellb[(best * 25 + lane) * 1024] : -1e30f;
            float mx = lv;
            #pragma unroll
            for (int o = 16; o > 0; o >>= 1)
                mx = fmaxf(mx, __shfl_xor_sync(FULL, mx, o));
            float ex = (lane < NCC) ? __expf(lv - mx) : 0.0f;
            #pragma unroll
            for (int o = 16; o > 0; o >>= 1)
                ex += __shfl_xor_sync(FULL, ex, o);
            float lc = __shfl_sync(FULL, lv, cls);

            if (lane == 0) {
                float d0 = bx - tx, d1 = by - ty;
                float d2 = sqrtf(bw) - sqrtf(tw), d3 = sqrtf(bh) - sqrtf(th);
                boxl  += d0 * d0 + d1 * d1 + d2 * d2 + d3 * d3;
                confl += (pcb - 1.0f) * (pcb - 1.0f);
                noobj -= pcb * pcb;                    // remove best from noobj
                clsl  += mx + __logf(ex) - lc;
            }
        }
    }

    // ---- dense: grid-stride over all conf float4s ----
    {
        int gid = blockIdx.x * NTHR + tid;
        for (int t = gid; t < NF4; t += TOTTHR) {
            int b = t / (AA * 256);
            int rr = t - b * (AA * 256);
            int a = rr >> 8;
            int q = rr & 255;
            float4 v = ((const float4*)out)[(size_t)(b * 125 + a * 25 + NCC) * 256 + q];
            float s;
            s = sigm(v.x); noobj += s * s;
            s = sigm(v.y); noobj += s * s;
            s = sigm(v.z); noobj += s * s;
            s = sigm(v.w); noobj += s * s;
        }
    }

    // ---- block reduction ----
    #pragma unroll
    for (int off = 16; off > 0; off >>= 1) {
        boxl  += __shfl_down_sync(0xffffffffu, boxl,  off);
        confl += __shfl_down_sync(0xffffffffu, confl, off);
        noobj += __shfl_down_sync(0xffffffffu, noobj, off);
        clsl  += __shfl_down_sync(0xffffffffu, clsl,  off);
    }
    if (lane == 0) {
        sm[0][wid] = boxl; sm[1][wid] = confl;
        sm[2][wid] = noobj; sm[3][wid] = clsl;
    }
    __syncthreads();
    if (tid == 0) {
        float s0 = 0, s1 = 0, s2 = 0, s3 = 0;
        #pragma unroll
        for (int k = 0; k < 8; k++) {
            s0 += sm[0][k]; s1 += sm[1][k]; s2 += sm[2][k]; s3 += sm[3][k];
        }
        if (s0 != 0.0f) atomicAdd(&g_acc[0], s0);
        if (s1 != 0.0f) atomicAdd(&g_acc[1], s1);
        atomicAdd(&g_acc[2], s2);
        if (s3 != 0.0f) atomicAdd(&g_acc[3], s3);
        __threadfence();
        unsigned old = atomicInc(&g_cnt, GRID - 1);
        if (old == GRID - 1) {                  // last block finalizes
            volatile float* a = g_acc;
            dout[0] = a[0] * (5.0f / 256.0f);   // LAM_COORD / B
            dout[1] = a[1] * (1.0f / 256.0f);   // LAM_OBJ   / B
            dout[2] = a[2] * (0.5f / 256.0f);   // LAM_NOOBJ / B
            dout[3] = a[3] * (1.0f / 256.0f);   // LAM_CLS   / B
            g_acc[0] = 0.0f; g_acc[1] = 0.0f;   // reset for next replay
            g_acc[2] = 0.0f; g_acc[3] = 0.0f;
        }
    }
}

extern "C" void kernel_launch(void* const* d_in, const int* in_sizes, int n_in,
                              void* d_out, int out_size) {
    const float*  out_t      = (const float*)d_in[0];
    const float4* gt_boxes   = (const float4*)d_in[1];
    const float*  anchor     = (const float*)d_in[2];
    const int*    gt_classes = (const int*)d_in[3];
    const int*    num_box    = (const int*)d_in[4];
    float* dout = (float*)d_out;

    fused_loss_kernel<<<GRID, NTHR>>>(out_t, gt_boxes, anchor,
                                      gt_classes, num_box, dout);
}

// round 9
// speedup vs baseline: 1.4289x; 1.0172x over previous
#include <cuda_runtime.h>
#include <math.h>

#define BB   256
#define HH   32
#define WW   32
#define AA   5
#define NCC  20
#define MM   50
#define NOBJ (BB*MM)

#define GRID    640                    // <= 740 (5 blocks/SM) -> single wave
#define NTHR    256
#define NF4     (BB*AA*256)            // 327680 conf float4s = GRID*NTHR*2
#define HALF    (GRID*NTHR)            // 163840
#define OPB     20                     // 640*20 = 12800 objects exactly

// Zero-init at load; last block resets accumulators each launch -> replay-safe.
__device__ float    g_acc[4];
__device__ unsigned g_cnt;

__device__ __forceinline__ float sigm(float x) { return 1.0f / (1.0f + __expf(-x)); }

__device__ __forceinline__ const float4* conf_ptr(const float4* out4, int t) {
    int b = t / (AA * 256);
    int r = t - b * (AA * 256);
    int a = r >> 8;
    int q = r & 255;
    return out4 + (size_t)(b * 125 + a * 25 + NCC) * 256 + q;
}

__global__ void __launch_bounds__(256, 5)
fused_loss_kernel(const float* __restrict__ out,
                  const float4* __restrict__ gt_boxes,
                  const float* __restrict__ anchor,
                  const int* __restrict__ gt_classes,
                  const int* __restrict__ num_box,
                  float* __restrict__ dout) {
    __shared__ int    s_cell[2 * MM];
    __shared__ int    s_cls [2 * MM];
    __shared__ int    s_meta[OPB];      // packed b | cell<<8 | cls<<18
    __shared__ float4 s_box [OPB];      // tx,ty,tw,th (already *32)
    __shared__ int    s_nrec;
    __shared__ float  sm[4][8];

    int tid  = threadIdx.x;
    int lane = tid & 31;
    int wid  = tid >> 5;
    float boxl = 0.0f, confl = 0.0f, noobj = 0.0f, clsl = 0.0f;

    // ---- front-batched dense loads: in flight during phases 0-2 ----
    int gid = blockIdx.x * NTHR + tid;
    const float4* out4 = (const float4*)out;
    float4 v0 = *conf_ptr(out4, gid);
    float4 v1 = *conf_ptr(out4, gid + HALF);

    int i0 = blockIdx.x * OPB;
    int b0 = i0 / MM;

    // ---- phase 0: cells/classes of this block's (<=2) batches into smem ----
    if (tid == 0) s_nrec = 0;
    if (tid < 2 * MM) {
        int bb = b0 + tid / MM;
        int m2 = tid % MM;
        int cellv = -1, clsv = 0;
        if (bb < BB) {
            int nb = num_box[bb]; if (nb > MM) nb = MM;
            if (m2 < nb) {
                float4 bx = gt_boxes[bb * MM + m2];
                int gx = (int)(bx.x * 32.0f);
                int gy = (int)(bx.y * 32.0f);
                cellv = gy * WW + gx;
                clsv  = gt_classes[bb * MM + m2];
            }
        }
        s_cell[tid] = cellv;
        s_cls [tid] = clsv;
    }
    __syncthreads();

    // ---- phase 1: winner scan over smem + compaction (lanes 0-19, warp 0) ----
    if (tid < OPB) {
        int i = i0 + tid;
        int bb = i / MM;
        int m  = i - bb * MM;
        int base = (bb - b0) * MM;
        int mycell = s_cell[base + m];
        if (mycell >= 0) {
            int last = -1, minc = 1 << 30;
            #pragma unroll
            for (int m2 = 0; m2 < MM; m2++) {
                int c2 = s_cell[base + m2];
                if (c2 == mycell) {
                    last = m2;
                    int cc = s_cls[base + m2];
                    minc = (cc < minc) ? cc : minc;
                }
            }
            if (last == m) {
                int r = atomicAdd(&s_nrec, 1);
                s_meta[r] = bb | (mycell << 8) | (minc << 18);
                float4 bx = gt_boxes[i];
                s_box[r] = make_float4(bx.x * 32.0f, bx.y * 32.0f,
                                       bx.z * 32.0f, bx.w * 32.0f);
            }
        }
    }
    __syncthreads();

    // ---- phase 2: warp-cooperative winner processing ----
    {
        const unsigned FULL = 0xffffffffu;
        int a_id = lane / 5, ch = lane - a_id * 5;
        float anc = 1.0f;
        if (lane < 25 && ch >= 3) anc = anchor[2 * a_id + (ch - 3)];
        int nrec = s_nrec;
        for (int r = wid; r < nrec; r += 8) {
            int   meta = s_meta[r];
            float4 tb  = s_box[r];
            int bb   = meta & 255;
            int cell = (meta >> 8) & 1023;
            int cls  = (meta >> 18) & 31;
            const float* cellb = out + (size_t)bb * 128000 + cell;
            int wq = cell & 31, hq = (cell >> 5) & 31;

            float v = 0.0f;
            if (lane < 25) v = cellb[(a_id * 25 + NCC + ch) * 1024];
            float tval = (ch <= 2) ? sigm(v) : __expf(v) * anc;
            float s1 = __shfl_sync(FULL, tval, lane + 1);
            float s2 = __shfl_sync(FULL, tval, lane + 2);
            float s3 = __shfl_sync(FULL, tval, lane + 3);
            float s4 = __shfl_sync(FULL, tval, lane + 4);

            float tx = tb.x, ty = tb.y, tw = tb.z, th = tb.w;
            float tx1 = tx - tw * 0.5f, ty1 = ty - th * 0.5f;
            float tx2 = tx + tw * 0.5f, ty2 = ty + th * 0.5f;
            float tarea = tw * th;

            float iou = -2.0f, px = 0, py = 0, pw = 0, ph = 0, pconf = 0;
            if (lane < 25 && ch == 0) {
                pconf = tval;
                px = (float)wq + s1; py = (float)hq + s2;
                pw = s3; ph = s4;
                float ax1 = px - pw * 0.5f, ay1 = py - ph * 0.5f;
                float ax2 = px + pw * 0.5f, ay2 = py + ph * 0.5f;
                float iw = fmaxf(fminf(ax2, tx2) - fmaxf(ax1, tx1), 0.0f);
                float ih = fmaxf(fminf(ay2, ty2) - fmaxf(ay1, ty1), 0.0f);
                float inter = iw * ih;
                float uni = pw * ph + tarea - inter;
                iou = inter / fmaxf(uni, 1e-10f);
            }
            float bi = -1.0f; int best = 0;
            float bx = 0, by = 0, bw = 0, bh = 0, pcb = 0;
            #pragma unroll
            for (int a = 0; a < AA; a++) {
                float ia = __shfl_sync(FULL, iou,   a * 5);
                float xa = __shfl_sync(FULL, px,    a * 5);
                float ya = __shfl_sync(FULL, py,    a * 5);
                float wa = __shfl_sync(FULL, pw,    a * 5);
                float ha = __shfl_sync(FULL, ph,    a * 5);
                float ca = __shfl_sync(FULL, pconf, a * 5);
                if (ia > bi) { bi = ia; best = a; bx = xa; by = ya; bw = wa; bh = ha; pcb = ca; }
            }

            float lv = (lane < NCC) ? cellb[(best * 25 + lane) * 1024] : -1e30f;
            float mx = lv;
            #pragma unroll
            for (int o = 16; o > 0; o >>= 1)
                mx = fmaxf(mx, __shfl_xor_sync(FULL, mx, o));
            float ex = (lane < NCC) ? __expf(lv - mx) : 0.0f;
            #pragma unroll
            for (int o = 16; o > 0; o >>= 1)
                ex += __shfl_xor_sync(FULL, ex, o);
            float lc = __shfl_sync(FULL, lv, cls);

            if (lane == 0) {
                float d0 = bx - tx, d1 = by - ty;
                float d2 = sqrtf(bw) - sqrtf(tw), d3 = sqrtf(bh) - sqrtf(th);
                boxl  += d0 * d0 + d1 * d1 + d2 * d2 + d3 * d3;
                confl += (pcb - 1.0f) * (pcb - 1.0f);
                noobj -= pcb * pcb;
                clsl  += mx + __logf(ex) - lc;
            }
        }
    }

    // ---- consume the front-batched dense loads ----
    {
        float s;
        s = sigm(v0.x); noobj += s * s;
        s = sigm(v0.y); noobj += s * s;
        s = sigm(v0.z); noobj += s * s;
        s = sigm(v0.w); noobj += s * s;
        s = sigm(v1.x); noobj += s * s;
        s = sigm(v1.y); noobj += s * s;
        s = sigm(v1.z); noobj += s * s;
        s = sigm(v1.w); noobj += s * s;
    }

    // ---- block reduction ----
    #pragma unroll
    for (int off = 16; off > 0; off >>= 1) {
        boxl  += __shfl_down_sync(0xffffffffu, boxl,  off);
        confl += __shfl_down_sync(0xffffffffu, confl, off);
        noobj += __shfl_down_sync(0xffffffffu, noobj, off);
        clsl  += __shfl_down_sync(0xffffffffu, clsl,  off);
    }
    if (lane == 0) {
        sm[0][wid] = boxl; sm[1][wid] = confl;
        sm[2][wid] = noobj; sm[3][wid] = clsl;
    }
    __syncthreads();
    if (tid == 0) {
        float s0 = 0, s1 = 0, s2 = 0, s3 = 0;
        #pragma unroll
        for (int k = 0; k < 8; k++) {
            s0 += sm[0][k]; s1 += sm[1][k]; s2 += sm[2][k]; s3 += sm[3][k];
        }
        if (s0 != 0.0f) atomicAdd(&g_acc[0], s0);
        if (s1 != 0.0f) atomicAdd(&g_acc[1], s1);
        atomicAdd(&g_acc[2], s2);
        if (s3 != 0.0f) atomicAdd(&g_acc[3], s3);
        __threadfence();
        unsigned old = atomicInc(&g_cnt, GRID - 1);
        if (old == GRID - 1) {                  // last block finalizes
            volatile float* a = g_acc;
            dout[0] = a[0] * (5.0f / 256.0f);   // LAM_COORD / B
            dout[1] = a[1] * (1.0f / 256.0f);   // LAM_OBJ   / B
            dout[2] = a[2] * (0.5f / 256.0f);   // LAM_NOOBJ / B
            dout[3] = a[3] * (1.0f / 256.0f);   // LAM_CLS   / B
            g_acc[0] = 0.0f; g_acc[1] = 0.0f;   // reset for next replay
            g_acc[2] = 0.0f; g_acc[3] = 0.0f;
        }
    }
}

extern "C" void kernel_launch(void* const* d_in, const int* in_sizes, int n_in,
                              void* d_out, int out_size) {
    const float*  out_t      = (const float*)d_in[0];
    const float4* gt_boxes   = (const float4*)d_in[1];
    const float*  anchor     = (const float*)d_in[2];
    const int*    gt_classes = (const int*)d_in[3];
    const int*    num_box    = (const int*)d_in[4];
    float* dout = (float*)d_out;

    fused_loss_kernel<<<GRID, NTHR>>>(out_t, gt_boxes, anchor,
                                      gt_classes, num_box, dout);
}